// round 14
// baseline (speedup 1.0000x reference)
#include <cuda_runtime.h>
#include <cuda_fp16.h>
#include <cstdint>
#include <math.h>

#define TOKENS 8192
#define DMODEL 1024
#define DFF    4096
#define RANK   128
#define MT     64
#define THREADS 512

// word strides (1 word = half2); ≡16 (mod 32) -> conflict-free LDS.128
#define S80 80       // rows of 64 data words (K=128)
#define S48 48       // rows of 32 data words (K=64)

// smem word offsets
#define W_SA 0            // t1/t2 tile: 64 x 80 = 5120
#define W_SH 5120         // h tile:     64 x 48 = 3072
#define W_B  8192         // 3 staging buffers
#define BSZ  11264        // per buffer: V1(64x80=5120) + U2(128x48=6144)
#define BU_OFF 5120       // U2 offset inside stage-2 buffer
#define BX_U1  3072       // U1 offset inside stage-1 buffer (x at 0, 64x48)
#define SMEM_WORDS (8192 + 3*BSZ)   // 41984 words = 167936 B -> 1 CTA/SM

// ---- half2-packed, k-permuted weight scratch (prep outputs) ----
__device__ uint32_t g_v1h[DFF * 64];     // cfc_V    [f][word(r)]
__device__ uint32_t g_v2h[DMODEL * 64];  // cp_V     [d][word(r)]
__device__ uint32_t g_u1th[RANK * 512];  // (U1*S)^T [r][word(d)]
__device__ uint32_t g_u2th[RANK * 2048]; // (U2*S2)^T[r][word(f)]

__device__ __forceinline__ int pw(int w) {     // permute low 4 bits (self-inverse)
    return (w & ~15) | ((w & 3) << 2) | ((w >> 2) & 3);
}
__device__ __forceinline__ uint32_t pk(float lo, float hi) {
    __half2 h = __floats2half2_rn(lo, hi);
    return *(uint32_t*)&h;
}
__device__ __forceinline__ float gelu_exact(float v) {
    return 0.5f * v * (1.f + erff(v * 0.7071067811865476f));
}
__device__ __forceinline__ void mma16(float* c,
                                      uint32_t a0, uint32_t a1, uint32_t a2, uint32_t a3,
                                      uint32_t b0, uint32_t b1) {
    asm volatile(
        "mma.sync.aligned.m16n8k16.row.col.f32.f16.f16.f32 "
        "{%0,%1,%2,%3}, {%4,%5,%6,%7}, {%8,%9}, {%0,%1,%2,%3};\n"
        : "+f"(c[0]), "+f"(c[1]), "+f"(c[2]), "+f"(c[3])
        : "r"(a0), "r"(a1), "r"(a2), "r"(a3), "r"(b0), "r"(b1));
}
__device__ __forceinline__ void cpa16(uint32_t dst, const void* src) {
    asm volatile("cp.async.cg.shared.global [%0], [%1], 16;\n" :: "r"(dst), "l"(src) : "memory");
}
#define CPA_COMMIT() asm volatile("cp.async.commit_group;\n" ::: "memory")
#define CPA_WAIT1()  asm volatile("cp.async.wait_group 1;\n" ::: "memory")
#define BAR_RG(rg)   asm volatile("bar.sync %0, 256;\n" :: "r"(1 + (rg)) : "memory")

// Warp GEMM: 32 A-rows at mrow, NT n-tiles of 8, K = KG*32.
// One LDS.128 feeds TWO m16n8k16 steps. acc[2*NT][4].
template<int NT, int KG, int SA_, int SB_>
__device__ __forceinline__ void gemm16(const uint32_t* __restrict__ A,
                                       const uint32_t* __restrict__ B,
                                       int mrow, int ncol, int qr, int qc, float (*acc)[4])
{
    #pragma unroll
    for (int kg = 0; kg < KG; kg++) {
        const int kb = kg * 16 + qc * 4;
        uint4 a0 = *(const uint4*)(A + (mrow + qr)      * SA_ + kb);
        uint4 a1 = *(const uint4*)(A + (mrow + qr + 8)  * SA_ + kb);
        uint4 a2 = *(const uint4*)(A + (mrow + qr + 16) * SA_ + kb);
        uint4 a3 = *(const uint4*)(A + (mrow + qr + 24) * SA_ + kb);
        uint4 b[NT];
        #pragma unroll
        for (int nt = 0; nt < NT; nt++)
            b[nt] = *(const uint4*)(B + (ncol + nt * 8 + qr) * SB_ + kb);
        #pragma unroll
        for (int nt = 0; nt < NT; nt++) {
            mma16(acc[nt],      a0.x, a1.x, a0.y, a1.y, b[nt].x, b[nt].y);
            mma16(acc[nt],      a0.z, a1.z, a0.w, a1.w, b[nt].z, b[nt].w);
            mma16(acc[NT + nt], a2.x, a3.x, a2.y, a3.y, b[nt].x, b[nt].y);
            mma16(acc[NT + nt], a2.z, a3.z, a2.w, a3.w, b[nt].z, b[nt].w);
        }
    }
}

// ---------------- prep: fp16-pack, fold S, transpose, k-permute (proven) ----------------
__global__ void prep_w_kernel(const float* __restrict__ cfc_U, const float* __restrict__ cfc_S,
                              const float* __restrict__ cfc_V,
                              const float* __restrict__ cp_U,  const float* __restrict__ cp_S,
                              const float* __restrict__ cp_V) {
    int b = blockIdx.x, t = threadIdx.x;
    if (b < 512) {
        int i = b * 256 + t;
        int row = i >> 5, j = i & 31;
        float4 v = ((const float4*)cfc_V)[i];
        uint32_t* d = g_v1h + (size_t)row * 64;
        d[pw(2 * j)]     = pk(v.x, v.y);
        d[pw(2 * j + 1)] = pk(v.z, v.w);
    } else if (b < 640) {
        int i = (b - 512) * 256 + t;
        int row = i >> 5, j = i & 31;
        float4 v = ((const float4*)cp_V)[i];
        uint32_t* d = g_v2h + (size_t)row * 64;
        d[pw(2 * j)]     = pk(v.x, v.y);
        d[pw(2 * j + 1)] = pk(v.z, v.w);
    } else if (b < 896) {
        int o = (b - 640) * 256 + t;
        int r = o >> 9, w = o & 511;
        int wl = pw(w);
        float s = cfc_S[r];
        g_u1th[o] = pk(cfc_U[(size_t)(2 * wl) * RANK + r] * s,
                       cfc_U[(size_t)(2 * wl + 1) * RANK + r] * s);
    } else {
        int o = (b - 896) * 256 + t;
        int r = o >> 11, w = o & 2047;
        int wl = pw(w);
        float s = cp_S[r];
        g_u2th[o] = pk(cp_U[(size_t)(2 * wl) * RANK + r] * s,
                       cp_U[(size_t)(2 * wl + 1) * RANK + r] * s);
    }
}

// ---------------- main fused kernel: 512 threads, 16 warps ----------------
__global__ void __launch_bounds__(THREADS, 1)
fused_lowrank_mlp_kernel(const float* __restrict__ x,
                         const float* __restrict__ cfc_b,
                         const float* __restrict__ cp_b,
                         float* __restrict__ out)
{
    extern __shared__ uint32_t sm[];
    uint32_t* SA = sm + W_SA;
    uint32_t* SH = sm + W_SH;
    uint32_t* B_[3] = { sm + W_B, sm + W_B + BSZ, sm + W_B + 2 * BSZ };
    const uint32_t smb = (uint32_t)__cvta_generic_to_shared(sm);
    const uint32_t BA[3] = { smb + W_B * 4u, smb + (W_B + BSZ) * 4u, smb + (W_B + 2 * BSZ) * 4u };

    const int tid  = threadIdx.x;
    const int lane = tid & 31;
    const int warp = tid >> 5;          // 0..15
    const int qr   = lane >> 2;
    const int qc   = lane & 3;
    const int rg   = warp >> 3;         // 2 row groups of 32 rows
    const int cg   = warp & 7;          // 8 col groups
    const int mrow = rg * 32;
    const int m0   = blockIdx.x * MT;

    // ---- staging helpers (512 threads: 2 cp.async each per 1024-uint4 tile) ----
    auto stage_u1 = [&](int ci, int bi) {          // U1 chunk [128 r x 32 w]
        #pragma unroll
        for (int i = 0; i < 2; i++) {
            int u = tid + i * THREADS; int row = u >> 3, q = u & 7;
            cpa16(BA[bi] + (BX_U1 + row * S48 + q * 4) * 4u,
                  g_u1th + (size_t)row * 512 + ci * 32 + q * 4);
        }
    };
    auto stage_2 = [&](int it, int bi) {           // V1 [64 f x 64 w] + U2 [128 r x 32 w]
        #pragma unroll
        for (int i = 0; i < 2; i++) {
            int u = tid + i * THREADS; int row = u >> 4, q = u & 15;
            cpa16(BA[bi] + (row * S80 + q * 4) * 4u,
                  g_v1h + (size_t)(it * 64 + row) * 64 + q * 4);
        }
        #pragma unroll
        for (int i = 0; i < 2; i++) {
            int u = tid + i * THREADS; int row = u >> 3, q = u & 7;
            cpa16(BA[bi] + (BU_OFF + row * S48 + q * 4) * 4u,
                  g_u2th + (size_t)row * 2048 + it * 32 + q * 4);
        }
    };
    auto stage_3 = [&](int dc, int bi) {           // V2 [64 d x 64 w]
        #pragma unroll
        for (int i = 0; i < 2; i++) {
            int u = tid + i * THREADS; int row = u >> 4, q = u & 15;
            cpa16(BA[bi] + (row * S80 + q * 4) * 4u,
                  g_v2h + (size_t)(dc * 64 + row) * 64 + q * 4);
        }
    };

    // x chunk [64 tok x 64 d]: LDG float4 -> regs; STS packed+permuted half2
    float4 xr[2];
    auto ldx = [&](int ci) {
        if (ci < 16) {
            #pragma unroll
            for (int i = 0; i < 2; i++) {
                int idx = tid + i * THREADS; int row = idx >> 4, j = idx & 15;
                xr[i] = *(const float4*)(x + (size_t)(m0 + row) * DMODEL + ci * 64 + j * 4);
            }
        }
    };
    auto stx = [&](uint32_t* buf) {
        #pragma unroll
        for (int i = 0; i < 2; i++) {
            int idx = tid + i * THREADS; int row = idx >> 4, j = idx & 15;
            uint32_t* d = buf + row * S48;
            d[pw(2 * j)]     = pk(xr[i].x, xr[i].y);
            d[pw(2 * j + 1)] = pk(xr[i].z, xr[i].w);
        }
    };

    // ================= Phase 1: t1[64x128] = x @ (U1*S); warp tile 32x16 =================
    float acc1[4][4];
    #pragma unroll
    for (int i = 0; i < 4; i++)
        #pragma unroll
        for (int j = 0; j < 4; j++) acc1[i][j] = 0.f;

    ldx(0); stx(B_[0]); stage_u1(0, 0); CPA_COMMIT();
    ldx(1); stx(B_[1]); stage_u1(1, 1); CPA_COMMIT();
    ldx(2);

    for (int ci = 0; ci < 16; ci++) {
        CPA_WAIT1(); __syncthreads();
        if (ci + 2 < 16) { stx(B_[(ci + 2) % 3]); stage_u1(ci + 2, (ci + 2) % 3); }
        CPA_COMMIT();
        ldx(ci + 3);
        const uint32_t* buf = B_[ci % 3];
        gemm16<2, 2, S48, S48>(buf, buf + BX_U1, mrow, cg * 16, qr, qc, acc1);
    }
    __syncthreads();

    // t1 epilogue -> SA (packed half2, k-permuted)
    #pragma unroll
    for (int nt = 0; nt < 2; nt++) {
        int p = pw(cg * 8 + nt * 4 + qc);
        SA[(mrow + qr) * S80 + p]      = pk(acc1[nt][0], acc1[nt][1]);
        SA[(mrow + qr + 8) * S80 + p]  = pk(acc1[nt][2], acc1[nt][3]);
        SA[(mrow + qr + 16) * S80 + p] = pk(acc1[2 + nt][0], acc1[2 + nt][1]);
        SA[(mrow + qr + 24) * S80 + p] = pk(acc1[2 + nt][2], acc1[2 + nt][3]);
    }

    stage_2(0, 0); CPA_COMMIT();
    stage_2(1, 1); CPA_COMMIT();

    // ===== Phase 2: 64 f-chunks of 64; t2[64x128] in registers (warp tile 32x16) =====
    float t2a[4][4];
    #pragma unroll
    for (int i = 0; i < 4; i++)
        #pragma unroll
        for (int j = 0; j < 4; j++) t2a[i][j] = 0.f;

    for (int it = 0; it < 64; it++) {
        const uint32_t* buf = B_[it % 3];
        CPA_WAIT1(); __syncthreads();
        if (it + 2 < 64) stage_2(it + 2, (it + 2) % 3);   // freed by GEMM3(it-1), covered by sync
        CPA_COMMIT();

        // GEMM2: h[64x64] = t1 @ V1c^T (K=128); warp tile 32x8
        float ha[2][4];
        #pragma unroll
        for (int i = 0; i < 2; i++)
            #pragma unroll
            for (int j = 0; j < 4; j++) ha[i][j] = 0.f;
        gemm16<1, 4, S80, S80>(SA, buf, mrow, cg * 8, qr, qc, ha);

        // bias + exact GELU -> SH (packed half2, permuted)
        {
            int c0 = cg * 8 + 2 * qc;
            int fb = it * 64 + c0;
            float b0 = __ldg(cfc_b + fb), b1 = __ldg(cfc_b + fb + 1);
            int p = pw(cg * 4 + qc);
            SH[(mrow + qr) * S48 + p] =
                pk(gelu_exact(ha[0][0] + b0), gelu_exact(ha[0][1] + b1));
            SH[(mrow + qr + 8) * S48 + p] =
                pk(gelu_exact(ha[0][2] + b0), gelu_exact(ha[0][3] + b1));
            SH[(mrow + qr + 16) * S48 + p] =
                pk(gelu_exact(ha[1][0] + b0), gelu_exact(ha[1][1] + b1));
            SH[(mrow + qr + 24) * S48 + p] =
                pk(gelu_exact(ha[1][2] + b0), gelu_exact(ha[1][3] + b1));
        }
        BAR_RG(rg);   // 256-thread barrier: same-row-group warps produce the h rows read below

        // GEMM3: t2[64x128] += h @ (U2*S2)c (K=64); warp tile 32x16
        gemm16<2, 2, S48, S48>(SH, buf + BU_OFF, mrow, cg * 16, qr, qc, t2a);
    }
    __syncthreads();

    // t2 epilogue -> SA (reuse)
    #pragma unroll
    for (int nt = 0; nt < 2; nt++) {
        int p = pw(cg * 8 + nt * 4 + qc);
        SA[(mrow + qr) * S80 + p]      = pk(t2a[nt][0], t2a[nt][1]);
        SA[(mrow + qr + 8) * S80 + p]  = pk(t2a[nt][2], t2a[nt][3]);
        SA[(mrow + qr + 16) * S80 + p] = pk(t2a[2 + nt][0], t2a[2 + nt][1]);
        SA[(mrow + qr + 24) * S80 + p] = pk(t2a[2 + nt][2], t2a[2 + nt][3]);
    }

    stage_3(0, 0); CPA_COMMIT();
    stage_3(1, 1); CPA_COMMIT();

    // ================= Phase 3: out = t2 @ V2^T + b2; warp tile 32x8 =================
    for (int dc = 0; dc < 16; dc++) {
        CPA_WAIT1(); __syncthreads();
        if (dc + 2 < 16) stage_3(dc + 2, (dc + 2) % 3);
        CPA_COMMIT();

        float oa[2][4];
        #pragma unroll
        for (int i = 0; i < 2; i++)
            #pragma unroll
            for (int j = 0; j < 4; j++) oa[i][j] = 0.f;
        gemm16<1, 4, S80, S80>(SA, B_[dc % 3], mrow, cg * 8, qr, qc, oa);

        {
            int c0 = cg * 8 + 2 * qc;
            int db = dc * 64 + c0;
            float b0 = __ldg(cp_b + db), b1 = __ldg(cp_b + db + 1);
            int r0 = m0 + mrow + qr;
            *(float2*)(out + (size_t)r0 * DMODEL + db) =
                make_float2(oa[0][0] + b0, oa[0][1] + b1);
            *(float2*)(out + (size_t)(r0 + 8) * DMODEL + db) =
                make_float2(oa[0][2] + b0, oa[0][3] + b1);
            *(float2*)(out + (size_t)(r0 + 16) * DMODEL + db) =
                make_float2(oa[1][0] + b0, oa[1][1] + b1);
            *(float2*)(out + (size_t)(r0 + 24) * DMODEL + db) =
                make_float2(oa[1][2] + b0, oa[1][3] + b1);
        }
    }
}

extern "C" void kernel_launch(void* const* d_in, const int* in_sizes, int n_in,
                              void* d_out, int out_size)
{
    const float* x     = (const float*)d_in[0];
    const float* cfc_U = (const float*)d_in[1];
    const float* cfc_S = (const float*)d_in[2];
    const float* cfc_V = (const float*)d_in[3];
    const float* cfc_b = (const float*)d_in[4];
    const float* cp_U  = (const float*)d_in[5];
    const float* cp_S  = (const float*)d_in[6];
    const float* cp_V  = (const float*)d_in[7];
    const float* cp_b  = (const float*)d_in[8];
    float* out = (float*)d_out;

    prep_w_kernel<<<1920, 256>>>(cfc_U, cfc_S, cfc_V, cp_U, cp_S, cp_V);

    const int smem_bytes = SMEM_WORDS * 4;   // 167936
    cudaFuncSetAttribute(fused_lowrank_mlp_kernel,
                         cudaFuncAttributeMaxDynamicSharedMemorySize, smem_bytes);
    fused_lowrank_mlp_kernel<<<TOKENS / MT, THREADS, smem_bytes>>>(x, cfc_b, cp_b, out);
}

// round 16
// speedup vs baseline: 1.0861x; 1.0861x over previous
#include <cuda_runtime.h>
#include <cuda_fp16.h>
#include <cstdint>
#include <math.h>

#define TOKENS 8192
#define DMODEL 1024
#define DFF    4096
#define RANK   128
#define MT     64

// ---- smem word map ----
#define W_MB 0             // 3 mbarriers (8B each), padded to 16 words
#define W_SA 16            // t1/t2: 64 x 80 (padded, pw) = 5120
#define W_SH 5136          // h:     64 x 48 (padded, pw) = 3072
#define W_B  8208          // 3 staging buffers (dense, swizzled)
#define BSZ  8192          // per buffer: slotA 4096 w + slotB 4096 w
#define SLOTB 4096
#define SMEM_WORDS 32784   // 131136 B
#define S80 80
#define S48 48

// ---- chunk-contiguous fp16 scratch (prep outputs; dense + pw + unit-swizzle) ----
__device__ uint32_t g_xh[128 * 16 * 64 * 32]; // [tile][chunk][row64][word32]
__device__ uint32_t g_v1[64 * 64 * 64];       // [it][f-row][word]   (K=128 -> 64 w)
__device__ uint32_t g_u2[64 * 128 * 32];      // [it][r-row][word]   (K=64  -> 32 w)
__device__ uint32_t g_u1[16 * 128 * 32];      // [ci][r-row][word]
__device__ uint32_t g_v2[16 * 64 * 64];       // [dc][d-row][word]

__device__ __forceinline__ int pw(int w) {    // permute low 4 bits (self-inverse)
    return (w & ~15) | ((w & 3) << 2) | ((w >> 2) & 3);
}
__device__ __forceinline__ uint32_t pk(float lo, float hi) {
    __half2 h = __floats2half2_rn(lo, hi);
    return *(uint32_t*)&h;
}
__device__ __forceinline__ float gelu_exact(float v) {
    return 0.5f * v * (1.f + erff(v * 0.7071067811865476f));
}
__device__ __forceinline__ void mma16(float* c,
                                      uint32_t a0, uint32_t a1, uint32_t a2, uint32_t a3,
                                      uint32_t b0, uint32_t b1) {
    asm volatile(
        "mma.sync.aligned.m16n8k16.row.col.f32.f16.f16.f32 "
        "{%0,%1,%2,%3}, {%4,%5,%6,%7}, {%8,%9}, {%0,%1,%2,%3};\n"
        : "+f"(c[0]), "+f"(c[1]), "+f"(c[2]), "+f"(c[3])
        : "r"(a0), "r"(a1), "r"(a2), "r"(a3), "r"(b0), "r"(b1));
}

#define BAR_RG(rg) asm volatile("bar.sync %0, 128;\n" :: "r"(1 + (rg)) : "memory")
#define MBAR_INIT(m, c) asm volatile("mbarrier.init.shared.b64 [%0], %1;" :: "r"(m), "r"(c) : "memory")
#define MBAR_EXPECT(m, bytes) asm volatile("mbarrier.arrive.expect_tx.shared.b64 _, [%0], %1;" :: "r"(m), "r"(bytes) : "memory")
#define TMA1D(dst, src, bytes, bar) \
    asm volatile("cp.async.bulk.shared::cluster.global.mbarrier::complete_tx::bytes [%0], [%1], %2, [%3];" \
        :: "r"(dst), "l"(src), "r"(bytes), "r"(bar) : "memory")

#define MBAR_WAIT(mb, par) do {                                            \
    uint32_t _m = (mb), _p = (par), _d;                                    \
    asm volatile("{\n\t.reg .pred p;\n\t"                                  \
        "mbarrier.try_wait.parity.acquire.cta.shared::cta.b64 p, [%1], %2;\n\t" \
        "selp.b32 %0, 1, 0, p;\n\t}" : "=r"(_d) : "r"(_m), "r"(_p) : "memory"); \
    if (!_d) {                                                             \
        asm volatile("{\n\t.reg .pred P1;\n\t"                             \
            "WL_%=:\n\t"                                                   \
            "mbarrier.try_wait.parity.acquire.cta.shared::cta.b64 P1, [%0], %1, 0x989680;\n\t" \
            "@P1 bra.uni WD_%=;\n\t"                                       \
            "bra.uni WL_%=;\n\t"                                           \
            "WD_%=:\n\t}" :: "r"(_m), "r"(_p) : "memory");                 \
    }                                                                      \
} while (0)

// Warp GEMM: 32 A-rows at mrow, NT n-tiles of 8, K = KG*32.
// AD: A dense+swizzled (AW words/row) vs padded (stride AW, pw offsets).
// B always dense+swizzled (BW words/row). One LDS.128 feeds two k16 steps.
template<int NT, int KG, bool AD, int AW, int BW>
__device__ __forceinline__ void gemmx(const uint32_t* __restrict__ A,
                                      const uint32_t* __restrict__ B,
                                      int mrow, int ncol, int qr, int qc, float (*acc)[4])
{
    #pragma unroll
    for (int kg = 0; kg < KG; kg++) {
        const int su = ((kg * 4 + qc) ^ qr) << 2;    // dense: rows ≡ qr (mod 8)
        const int ao = AD ? su : (kg * 16 + qc * 4);
        uint4 a0 = *(const uint4*)(A + (mrow + qr)      * AW + ao);
        uint4 a1 = *(const uint4*)(A + (mrow + qr + 8)  * AW + ao);
        uint4 a2 = *(const uint4*)(A + (mrow + qr + 16) * AW + ao);
        uint4 a3 = *(const uint4*)(A + (mrow + qr + 24) * AW + ao);
        uint4 b[NT];
        #pragma unroll
        for (int nt = 0; nt < NT; nt++)
            b[nt] = *(const uint4*)(B + (ncol + nt * 8 + qr) * BW + su);
        #pragma unroll
        for (int nt = 0; nt < NT; nt++) {
            mma16(acc[nt],      a0.x, a1.x, a0.y, a1.y, b[nt].x, b[nt].y);
            mma16(acc[nt],      a0.z, a1.z, a0.w, a1.w, b[nt].z, b[nt].w);
            mma16(acc[NT + nt], a2.x, a3.x, a2.y, a3.y, b[nt].x, b[nt].y);
            mma16(acc[NT + nt], a2.z, a3.z, a2.w, a3.w, b[nt].z, b[nt].w);
        }
    }
}

// ---------------- prep: x -> fp16 tiled/permuted/swizzled ----------------
__global__ void prep_x_kernel(const float* __restrict__ x) {
    int idx = blockIdx.x * 256 + threadIdx.x;      // 4,194,304 words
    int phys = idx & 31, row = (idx >> 5) & 63;
    int chunk = (idx >> 11) & 15, tile = idx >> 15;
    int p = (((phys >> 2) ^ (row & 7)) << 2) | (phys & 3);
    int w = pw(p);
    int tok = tile * 64 + row;
    int d0 = chunk * 64 + 2 * w;
    g_xh[idx] = pk(x[(size_t)tok * DMODEL + d0], x[(size_t)tok * DMODEL + d0 + 1]);
}

// ---------------- prep: weights (fold S, transpose, permute, swizzle) ----------------
__global__ void prep_w_kernel(const float* __restrict__ cfc_U, const float* __restrict__ cfc_S,
                              const float* __restrict__ cfc_V,
                              const float* __restrict__ cp_U,  const float* __restrict__ cp_S,
                              const float* __restrict__ cp_V) {
    int b = blockIdx.x, t = threadIdx.x;
    if (b < 1024) {                                  // g_v1 [it][f-row 64][w 64]
        int o = b * 256 + t;
        int phys = o & 63, row = (o >> 6) & 63, it = o >> 12;
        int p = (((phys >> 2) ^ (row & 7)) << 2) | (phys & 3);
        int w = pw(p);
        int f = it * 64 + row;
        g_v1[o] = pk(cfc_V[(size_t)f * RANK + 2 * w], cfc_V[(size_t)f * RANK + 2 * w + 1]);
    } else if (b < 2048) {                           // g_u2 [it][r 128][w 32]
        int o = (b - 1024) * 256 + t;
        int phys = o & 31, r = (o >> 5) & 127, it = o >> 12;
        int p = (((phys >> 2) ^ (r & 7)) << 2) | (phys & 3);
        int w = pw(p);
        int f0 = it * 64 + 2 * w;
        float s = cp_S[r];
        g_u2[o] = pk(cp_U[(size_t)f0 * RANK + r] * s, cp_U[(size_t)(f0 + 1) * RANK + r] * s);
    } else if (b < 2304) {                           // g_u1 [ci][r 128][w 32]
        int o = (b - 2048) * 256 + t;
        int phys = o & 31, r = (o >> 5) & 127, ci = o >> 12;
        int p = (((phys >> 2) ^ (r & 7)) << 2) | (phys & 3);
        int w = pw(p);
        int d0 = ci * 64 + 2 * w;
        float s = cfc_S[r];
        g_u1[o] = pk(cfc_U[(size_t)d0 * RANK + r] * s, cfc_U[(size_t)(d0 + 1) * RANK + r] * s);
    } else {                                         // g_v2 [dc][d-row 64][w 64]
        int o = (b - 2304) * 256 + t;
        int phys = o & 63, row = (o >> 6) & 63, dc = o >> 12;
        int p = (((phys >> 2) ^ (row & 7)) << 2) | (phys & 3);
        int w = pw(p);
        int d = dc * 64 + row;
        g_v2[o] = pk(cp_V[(size_t)d * RANK + 2 * w], cp_V[(size_t)d * RANK + 2 * w + 1]);
    }
}

// ---------------- main fused kernel: TMA-staged ----------------
__global__ void __launch_bounds__(256, 1)
fused_lowrank_mlp_kernel(const float* __restrict__ cfc_b,
                         const float* __restrict__ cp_b,
                         float* __restrict__ out)
{
    extern __shared__ uint32_t sm[];
    const uint32_t smb = (uint32_t)__cvta_generic_to_shared(sm);
    uint32_t* SA = sm + W_SA;
    uint32_t* SH = sm + W_SH;

    const int tid  = threadIdx.x;
    const int lane = tid & 31;
    const int warp = tid >> 5;
    const int qr   = lane >> 2;
    const int qc   = lane & 3;
    const int rg   = warp >> 2;          // 2 row groups of 32
    const int cg   = warp & 3;           // 4 col groups
    const int mrow = rg * 32;
    const int m0   = blockIdx.x * MT;

    auto mb   = [&](int i) { return smb + W_MB * 4u + i * 8u; };
    auto bufp = [&](int g) { return sm + W_B + (g % 3) * BSZ; };
    auto bufa = [&](int g) { return smb + (W_B + (g % 3) * BSZ) * 4u; };

    if (tid == 0) { MBAR_INIT(mb(0), 1); MBAR_INIT(mb(1), 1); MBAR_INIT(mb(2), 1); }
    __syncthreads();

    // producers (tid 0 only)
    auto stage1 = [&](int ci) {                      // global chunk ci
        uint32_t d = bufa(ci), bar = mb(ci % 3);
        MBAR_EXPECT(bar, 24576u);
        TMA1D(d, g_xh + ((size_t)blockIdx.x * 16 + ci) * 2048, 8192u, bar);
        TMA1D(d + SLOTB * 4u, g_u1 + (size_t)ci * 4096, 16384u, bar);
    };
    auto stage2 = [&](int c) {                       // global 16+c
        int g = 16 + c;
        uint32_t d = bufa(g), bar = mb(g % 3);
        MBAR_EXPECT(bar, 32768u);
        TMA1D(d, g_v1 + (size_t)c * 4096, 16384u, bar);
        TMA1D(d + SLOTB * 4u, g_u2 + (size_t)c * 4096, 16384u, bar);
    };
    auto stage3 = [&](int c) {                       // global 80+c
        int g = 80 + c;
        uint32_t d = bufa(g), bar = mb(g % 3);
        MBAR_EXPECT(bar, 16384u);
        TMA1D(d, g_v2 + (size_t)c * 4096, 16384u, bar);
    };

    int gc = 0;                                      // consumer chunk counter
    auto wait_chunk = [&]() {
        MBAR_WAIT(mb(gc % 3), (uint32_t)((gc / 3) & 1));
        gc++;
    };

    // ================= Phase 1: t1[64x128] = x @ (U1*S) =================
    float acc1[8][4];
    #pragma unroll
    for (int i = 0; i < 8; i++)
        #pragma unroll
        for (int j = 0; j < 4; j++) acc1[i][j] = 0.f;

    if (tid == 0) { stage1(0); stage1(1); }

    for (int ci = 0; ci < 16; ci++) {
        wait_chunk();
        __syncthreads();
        if (tid == 0 && ci + 2 < 16) stage1(ci + 2);
        const uint32_t* bp = bufp(ci);
        gemmx<4, 2, true, 32, 32>(bp, bp + SLOTB, mrow, cg * 32, qr, qc, acc1);
    }
    __syncthreads();
    if (tid == 0) { stage2(0); stage2(1); }

    // t1 epilogue -> SA (padded, pw)
    #pragma unroll
    for (int nt = 0; nt < 4; nt++) {
        int p = pw(cg * 16 + nt * 4 + qc);
        SA[(mrow + qr) * S80 + p]      = pk(acc1[nt][0], acc1[nt][1]);
        SA[(mrow + qr + 8) * S80 + p]  = pk(acc1[nt][2], acc1[nt][3]);
        SA[(mrow + qr + 16) * S80 + p] = pk(acc1[4 + nt][0], acc1[4 + nt][1]);
        SA[(mrow + qr + 24) * S80 + p] = pk(acc1[4 + nt][2], acc1[4 + nt][3]);
    }
    __syncthreads();

    // ===== Phase 2: 64 f-chunks; t2[64x128] in registers =====
    float t2a[8][4];
    #pragma unroll
    for (int i = 0; i < 8; i++)
        #pragma unroll
        for (int j = 0; j < 4; j++) t2a[i][j] = 0.f;

    for (int it = 0; it < 64; it++) {
        wait_chunk();
        __syncthreads();
        if (tid == 0 && it + 2 < 64) stage2(it + 2);
        const uint32_t* bp = bufp(16 + it);

        // GEMM2: h[64x64] = t1 @ V1c^T (K=128); warp tile 32x16
        float ha[4][4];
        #pragma unroll
        for (int i = 0; i < 4; i++)
            #pragma unroll
            for (int j = 0; j < 4; j++) ha[i][j] = 0.f;
        gemmx<2, 4, false, S80, 64>(SA, bp, mrow, cg * 16, qr, qc, ha);

        // bias + exact GELU -> SH (padded, pw)
        #pragma unroll
        for (int nt = 0; nt < 2; nt++) {
            int c0 = cg * 16 + nt * 8 + 2 * qc;
            int fb = it * 64 + c0;
            float b0 = __ldg(cfc_b + fb), b1 = __ldg(cfc_b + fb + 1);
            int p = pw(cg * 8 + nt * 4 + qc);
            SH[(mrow + qr) * S48 + p] =
                pk(gelu_exact(ha[nt][0] + b0), gelu_exact(ha[nt][1] + b1));
            SH[(mrow + qr + 8) * S48 + p] =
                pk(gelu_exact(ha[nt][2] + b0), gelu_exact(ha[nt][3] + b1));
            SH[(mrow + qr + 16) * S48 + p] =
                pk(gelu_exact(ha[2 + nt][0] + b0), gelu_exact(ha[2 + nt][1] + b1));
            SH[(mrow + qr + 24) * S48 + p] =
                pk(gelu_exact(ha[2 + nt][2] + b0), gelu_exact(ha[2 + nt][3] + b1));
        }
        BAR_RG(rg);

        // GEMM3: t2 += h @ (U2*S2)c (K=64); warp tile 32x32
        gemmx<4, 2, false, S48, 32>(SH, bp + SLOTB, mrow, cg * 32, qr, qc, t2a);
    }
    __syncthreads();
    if (tid == 0) { stage3(0); stage3(1); }

    // t2 epilogue -> SA (reuse)
    #pragma unroll
    for (int nt = 0; nt < 4; nt++) {
        int p = pw(cg * 16 + nt * 4 + qc);
        SA[(mrow + qr) * S80 + p]      = pk(t2a[nt][0], t2a[nt][1]);
        SA[(mrow + qr + 8) * S80 + p]  = pk(t2a[nt][2], t2a[nt][3]);
        SA[(mrow + qr + 16) * S80 + p] = pk(t2a[4 + nt][0], t2a[4 + nt][1]);
        SA[(mrow + qr + 24) * S80 + p] = pk(t2a[4 + nt][2], t2a[4 + nt][3]);
    }
    __syncthreads();

    // ================= Phase 3: out = t2 @ V2^T + b2 =================
    for (int dc = 0; dc < 16; dc++) {
        wait_chunk();
        __syncthreads();
        if (tid == 0 && dc + 2 < 16) stage3(dc + 2);

        float oa[4][4];
        #pragma unroll
        for (int i = 0; i < 4; i++)
            #pragma unroll
            for (int j = 0; j < 4; j++) oa[i][j] = 0.f;
        gemmx<2, 4, false, S80, 64>(SA, bufp(80 + dc), mrow, cg * 16, qr, qc, oa);

        #pragma unroll
        for (int nt = 0; nt < 2; nt++) {
            int c0 = cg * 16 + nt * 8 + 2 * qc;
            int db = dc * 64 + c0;
            float b0 = __ldg(cp_b + db), b1 = __ldg(cp_b + db + 1);
            int r0 = m0 + mrow + qr;
            *(float2*)(out + (size_t)r0 * DMODEL + db) =
                make_float2(oa[nt][0] + b0, oa[nt][1] + b1);
            *(float2*)(out + (size_t)(r0 + 8) * DMODEL + db) =
                make_float2(oa[nt][2] + b0, oa[nt][3] + b1);
            *(float2*)(out + (size_t)(r0 + 16) * DMODEL + db) =
                make_float2(oa[2 + nt][0] + b0, oa[2 + nt][1] + b1);
            *(float2*)(out + (size_t)(r0 + 24) * DMODEL + db) =
                make_float2(oa[2 + nt][2] + b0, oa[2 + nt][3] + b1);
        }
    }
}

extern "C" void kernel_launch(void* const* d_in, const int* in_sizes, int n_in,
                              void* d_out, int out_size)
{
    const float* x     = (const float*)d_in[0];
    const float* cfc_U = (const float*)d_in[1];
    const float* cfc_S = (const float*)d_in[2];
    const float* cfc_V = (const float*)d_in[3];
    const float* cfc_b = (const float*)d_in[4];
    const float* cp_U  = (const float*)d_in[5];
    const float* cp_S  = (const float*)d_in[6];
    const float* cp_V  = (const float*)d_in[7];
    const float* cp_b  = (const float*)d_in[8];
    float* out = (float*)d_out;

    prep_x_kernel<<<16384, 256>>>(x);
    prep_w_kernel<<<2560, 256>>>(cfc_U, cfc_S, cfc_V, cp_U, cp_S, cp_V);

    const int smem_bytes = SMEM_WORDS * 4;   // 131136
    cudaFuncSetAttribute(fused_lowrank_mlp_kernel,
                         cudaFuncAttributeMaxDynamicSharedMemorySize, smem_bytes);
    fused_lowrank_mlp_kernel<<<TOKENS / MT, 256, smem_bytes>>>(cfc_b, cp_b, out);
}